// round 1
// baseline (speedup 1.0000x reference)
#include <cuda_runtime.h>
#include <cstdint>
#include <math.h>

// Problem constants (fixed by setup_inputs)
#define TOKENS 8192       // B*S = 4*2048
#define DIM    1024       // D
#define CODES  16384      // NUM_CODES
#define KSEL   8          // kcodes

// ---------------------------------------------------------------------------
// Scratch (device globals: allocation-free per harness rules)
// ---------------------------------------------------------------------------
__device__ float g_c2[CODES];
__device__ float g_scores[(size_t)TOKENS * CODES];   // 512 MB
__device__ int   g_ids[TOKENS * KSEL];

// ---------------------------------------------------------------------------
// Kernel 1: codebook squared norms  c2[c] = sum_d cb[c][d]^2
// One block per code, 256 threads, each loads one float4.
// ---------------------------------------------------------------------------
__global__ __launch_bounds__(256) void c2_kernel(const float* __restrict__ cb) {
    const int code = blockIdx.x;
    const int t = threadIdx.x;
    float4 v = reinterpret_cast<const float4*>(cb + (size_t)code * DIM)[t];
    float s = v.x * v.x + v.y * v.y + v.z * v.z + v.w * v.w;
    #pragma unroll
    for (int o = 16; o > 0; o >>= 1)
        s += __shfl_down_sync(0xffffffffu, s, o);
    __shared__ float red[8];
    if ((t & 31) == 0) red[t >> 5] = s;
    __syncthreads();
    if (t == 0) {
        float tot = 0.f;
        #pragma unroll
        for (int i = 0; i < 8; i++) tot += red[i];
        g_c2[code] = tot;
    }
}

// ---------------------------------------------------------------------------
// Kernel 2: fp32 SGEMM epilogue-fused scores:
//   scores[m][n] = 2 * dot(X[m], CB[n]) - c2[n]
// 128x128 block tile, 256 threads, 8x8 per-thread micro-tile, k-step 8.
// ---------------------------------------------------------------------------
__global__ __launch_bounds__(256, 2) void gemm_scores_kernel(
    const float* __restrict__ X, const float* __restrict__ CB)
{
    __shared__ float As[8][128];
    __shared__ float Bs[8][128];

    const int tid = threadIdx.x;
    const int bm = blockIdx.y * 128;
    const int bn = blockIdx.x * 128;

    // Loader mapping: each thread loads one float4 of A and one of B per k-tile
    const int lrow = tid >> 1;          // 0..127
    const int lcol = (tid & 1) * 4;     // 0 or 4
    const float* Aptr = X  + (size_t)(bm + lrow) * DIM + lcol;
    const float* Bptr = CB + (size_t)(bn + lrow) * DIM + lcol;

    // Compute mapping: 16x16 thread grid, 8x8 per thread
    const int ty = tid >> 4;            // 0..15 -> M rows ty*8..ty*8+7
    const int tx = tid & 15;            // 0..15 -> N cols tx*8..tx*8+7

    float acc[8][8];
    #pragma unroll
    for (int i = 0; i < 8; i++)
        #pragma unroll
        for (int j = 0; j < 8; j++) acc[i][j] = 0.f;

    for (int k0 = 0; k0 < DIM; k0 += 8) {
        float4 av = *reinterpret_cast<const float4*>(Aptr + k0);
        float4 bv = *reinterpret_cast<const float4*>(Bptr + k0);
        As[lcol + 0][lrow] = av.x; As[lcol + 1][lrow] = av.y;
        As[lcol + 2][lrow] = av.z; As[lcol + 3][lrow] = av.w;
        Bs[lcol + 0][lrow] = bv.x; Bs[lcol + 1][lrow] = bv.y;
        Bs[lcol + 2][lrow] = bv.z; Bs[lcol + 3][lrow] = bv.w;
        __syncthreads();

        #pragma unroll
        for (int kk = 0; kk < 8; kk++) {
            float4 a0 = *reinterpret_cast<const float4*>(&As[kk][ty * 8]);
            float4 a1 = *reinterpret_cast<const float4*>(&As[kk][ty * 8 + 4]);
            float4 b0 = *reinterpret_cast<const float4*>(&Bs[kk][tx * 8]);
            float4 b1 = *reinterpret_cast<const float4*>(&Bs[kk][tx * 8 + 4]);
            float a[8] = {a0.x, a0.y, a0.z, a0.w, a1.x, a1.y, a1.z, a1.w};
            float b[8] = {b0.x, b0.y, b0.z, b0.w, b1.x, b1.y, b1.z, b1.w};
            #pragma unroll
            for (int i = 0; i < 8; i++)
                #pragma unroll
                for (int j = 0; j < 8; j++)
                    acc[i][j] += a[i] * b[j];
        }
        __syncthreads();
    }

    // Epilogue: score = 2*acc - c2[n]
    float c2r[8];
    #pragma unroll
    for (int j = 0; j < 8; j++) c2r[j] = g_c2[bn + tx * 8 + j];

    #pragma unroll
    for (int i = 0; i < 8; i++) {
        const int m = bm + ty * 8 + i;
        float* orow = g_scores + (size_t)m * CODES + bn + tx * 8;
        float4 r0, r1;
        r0.x = 2.f * acc[i][0] - c2r[0];
        r0.y = 2.f * acc[i][1] - c2r[1];
        r0.z = 2.f * acc[i][2] - c2r[2];
        r0.w = 2.f * acc[i][3] - c2r[3];
        r1.x = 2.f * acc[i][4] - c2r[4];
        r1.y = 2.f * acc[i][5] - c2r[5];
        r1.z = 2.f * acc[i][6] - c2r[6];
        r1.w = 2.f * acc[i][7] - c2r[7];
        reinterpret_cast<float4*>(orow)[0] = r0;
        reinterpret_cast<float4*>(orow)[1] = r1;
    }
}

// ---------------------------------------------------------------------------
// Kernel 3: per-token top-8 (value desc, tie -> lower index, matching
// jax.lax.top_k). One block (256 threads) per token.
// ---------------------------------------------------------------------------
__device__ __forceinline__ bool better(float va, int ia, float vb, int ib) {
    return (va > vb) || (va == vb && ia < ib);
}

__global__ __launch_bounds__(256) void topk_kernel(float* idsf, int* idsi) {
    const int token = blockIdx.x;
    const int t = threadIdx.x;
    const float* srow = g_scores + (size_t)token * CODES;

    float v[KSEL];
    int   ix[KSEL];
    #pragma unroll
    for (int i = 0; i < KSEL; i++) { v[i] = -INFINITY; ix[i] = 0x7fffffff; }

    // Strided local scan; index ascends within each thread, so equal-value
    // later candidates never replace earlier ones (tie-break preserved).
    for (int n = t; n < CODES; n += 256) {
        float s = srow[n];
        if (better(s, n, v[KSEL - 1], ix[KSEL - 1])) {
            v[KSEL - 1] = s; ix[KSEL - 1] = n;
            #pragma unroll
            for (int i = KSEL - 1; i > 0; i--) {
                if (better(v[i], ix[i], v[i - 1], ix[i - 1])) {
                    float tv = v[i]; v[i] = v[i - 1]; v[i - 1] = tv;
                    int ti = ix[i]; ix[i] = ix[i - 1]; ix[i - 1] = ti;
                }
            }
        }
    }

    __shared__ float sv[256 * KSEL];
    __shared__ int   si[256 * KSEL];
    #pragma unroll
    for (int i = 0; i < KSEL; i++) { sv[t * KSEL + i] = v[i]; si[t * KSEL + i] = ix[i]; }
    __syncthreads();

    // Tree merge of sorted-8 lists
    for (int stride = 128; stride >= 1; stride >>= 1) {
        if (t < stride) {
            float* a  = &sv[t * KSEL];
            int*   ai = &si[t * KSEL];
            float* b  = &sv[(t + stride) * KSEL];
            int*   bi = &si[(t + stride) * KSEL];
            float mv[KSEL]; int mi[KSEL];
            int i = 0, j = 0;
            #pragma unroll
            for (int o = 0; o < KSEL; o++) {
                bool ta = better(a[i], ai[i], b[j], bi[j]);
                mv[o] = ta ? a[i] : b[j];
                mi[o] = ta ? ai[i] : bi[j];
                if (ta) i++; else j++;
            }
            #pragma unroll
            for (int o = 0; o < KSEL; o++) { a[o] = mv[o]; ai[o] = mi[o]; }
        }
        __syncthreads();
    }

    if (t < KSEL) {
        int id = si[t];
        g_ids[token * KSEL + t] = id;
        if (idsf) idsf[token * KSEL + t] = (float)id;
        if (idsi) idsi[token * KSEL + t] = id;
    }
}

// ---------------------------------------------------------------------------
// Kernel 4: gather + mean:  out[token][d] = (1/8) * sum_k cb[id_k][d]
// One block per token, 256 threads x float4.
// ---------------------------------------------------------------------------
__global__ __launch_bounds__(256) void gather_kernel(
    const float* __restrict__ cb, float* __restrict__ out)
{
    const int token = blockIdx.x;
    const int t = threadIdx.x;
    __shared__ int ids[KSEL];
    if (t < KSEL) ids[t] = g_ids[token * KSEL + t];
    __syncthreads();

    float4 acc = make_float4(0.f, 0.f, 0.f, 0.f);
    #pragma unroll
    for (int k = 0; k < KSEL; k++) {
        float4 cv = reinterpret_cast<const float4*>(cb + (size_t)ids[k] * DIM)[t];
        acc.x += cv.x; acc.y += cv.y; acc.z += cv.z; acc.w += cv.w;
    }
    float4 r = make_float4(acc.x * 0.125f, acc.y * 0.125f,
                           acc.z * 0.125f, acc.w * 0.125f);
    reinterpret_cast<float4*>(out + (size_t)token * DIM)[t] = r;
}

// ---------------------------------------------------------------------------
// Launch
// ---------------------------------------------------------------------------
extern "C" void kernel_launch(void* const* d_in, const int* in_sizes, int n_in,
                              void* d_out, int out_size) {
    const float* inputs   = (const float*)d_in[0];
    const float* codebook = (const float*)d_in[1];
    float* out = (float*)d_out;

    c2_kernel<<<CODES, 256>>>(codebook);

    dim3 grid(CODES / 128, TOKENS / 128);
    gemm_scores_kernel<<<grid, 256>>>(inputs, codebook);

    const int OUT_MAIN = TOKENS * DIM;          // 8388608
    const int OUT_IDS  = TOKENS * KSEL;         // 65536

    float* idsf = nullptr;
    int*   idsi = nullptr;
    bool write_main = (out_size >= OUT_MAIN);
    if (out_size == OUT_MAIN + OUT_IDS) {
        idsf = out + (size_t)OUT_MAIN;          // ids appended, cast to f32
    } else if (out_size == OUT_IDS) {
        idsi = (int*)d_out;                     // ids-only output (int32)
    }

    topk_kernel<<<TOKENS, 256>>>(idsf, idsi);

    if (write_main)
        gather_kernel<<<TOKENS, 256>>>(codebook, out);
}

// round 5
// speedup vs baseline: 3.2945x; 3.2945x over previous
#include <cuda_runtime.h>
#include <cuda_bf16.h>
#include <cstdint>
#include <math.h>

#define TOKENS 8192
#define DIM    1024
#define CODES  16384
#define KSEL   8
#define NCAND  32

// ---------------------------------------------------------------------------
// Device scratch (no allocations allowed)
// ---------------------------------------------------------------------------
__device__ float          g_c2[CODES];
__device__ float          g_scores[(size_t)TOKENS * CODES];       // 512 MB
__device__ __nv_bfloat16  g_Xb[(size_t)TOKENS * DIM];             // 16 MB
__device__ __nv_bfloat16  g_CBb[(size_t)CODES * DIM];             // 32 MB
__device__ int            g_cand[TOKENS * NCAND];
__device__ int            g_ids[TOKENS * KSEL];

// ---------------------------------------------------------------------------
// Helpers
// ---------------------------------------------------------------------------
__device__ __forceinline__ uint32_t smem_to_u32(const void* p) {
    uint32_t a;
    asm("{ .reg .u64 t; cvta.to.shared.u64 t, %1; cvt.u32.u64 %0, t; }" : "=r"(a) : "l"(p));
    return a;
}
#define SWZ128(b) ((b) ^ (((b) >> 3) & 0x70))

__device__ __forceinline__ void cp_async16(uint32_t dst, const void* src) {
    asm volatile("cp.async.cg.shared.global [%0], [%1], 16;" :: "r"(dst), "l"(src) : "memory");
}
#define LDSM_X4(r0, r1, r2, r3, addr) \
    asm volatile("ldmatrix.sync.aligned.m8n8.x4.shared.b16 {%0,%1,%2,%3}, [%4];" \
        : "=r"(r0), "=r"(r1), "=r"(r2), "=r"(r3) : "r"(addr))

__device__ __forceinline__ void mma_bf16(float* c, const uint32_t* a, const uint32_t* b) {
    asm volatile(
        "mma.sync.aligned.m16n8k16.row.col.f32.bf16.bf16.f32 "
        "{%0,%1,%2,%3}, {%4,%5,%6,%7}, {%8,%9}, {%0,%1,%2,%3};"
        : "+f"(c[0]), "+f"(c[1]), "+f"(c[2]), "+f"(c[3])
        : "r"(a[0]), "r"(a[1]), "r"(a[2]), "r"(a[3]), "r"(b[0]), "r"(b[1]));
}

// ---------------------------------------------------------------------------
// fp32 -> bf16 converts
// ---------------------------------------------------------------------------
__global__ __launch_bounds__(256) void convX_kernel(const float* __restrict__ src) {
    size_t i = (size_t)blockIdx.x * 256 + threadIdx.x;
    float4 v = reinterpret_cast<const float4*>(src)[i];
    reinterpret_cast<__nv_bfloat162*>(g_Xb)[i * 2 + 0] = __floats2bfloat162_rn(v.x, v.y);
    reinterpret_cast<__nv_bfloat162*>(g_Xb)[i * 2 + 1] = __floats2bfloat162_rn(v.z, v.w);
}
__global__ __launch_bounds__(256) void convCB_kernel(const float* __restrict__ src) {
    size_t i = (size_t)blockIdx.x * 256 + threadIdx.x;
    float4 v = reinterpret_cast<const float4*>(src)[i];
    reinterpret_cast<__nv_bfloat162*>(g_CBb)[i * 2 + 0] = __floats2bfloat162_rn(v.x, v.y);
    reinterpret_cast<__nv_bfloat162*>(g_CBb)[i * 2 + 1] = __floats2bfloat162_rn(v.z, v.w);
}

// ---------------------------------------------------------------------------
// c2 norms (fp32, exact)
// ---------------------------------------------------------------------------
__global__ __launch_bounds__(256) void c2_kernel(const float* __restrict__ cb) {
    const int code = blockIdx.x;
    const int t = threadIdx.x;
    float4 v = reinterpret_cast<const float4*>(cb + (size_t)code * DIM)[t];
    float s = v.x * v.x + v.y * v.y + v.z * v.z + v.w * v.w;
    #pragma unroll
    for (int o = 16; o > 0; o >>= 1) s += __shfl_down_sync(0xffffffffu, s, o);
    __shared__ float red[8];
    if ((t & 31) == 0) red[t >> 5] = s;
    __syncthreads();
    if (t == 0) {
        float tot = 0.f;
        #pragma unroll
        for (int i = 0; i < 8; i++) tot += red[i];
        g_c2[code] = tot;
    }
}

// ---------------------------------------------------------------------------
// mma.sync bf16 GEMM: scores[m][n] = 2*dot(Xb[m], CBb[n]) - c2[n]
// CTA 128(M) x 256(N), 8 warps (warp tile 64x64), k-chunk 64, double buffer.
// ---------------------------------------------------------------------------
#define KC        64
#define NCHUNK    (DIM / KC)          // 16
#define A_BYTES   (128 * 128)         // 16 KB
#define B_BYTES   (256 * 128)         // 32 KB
#define OFF_C2S   0                   // 1 KB
#define OFF_A0    1024
#define OFF_A1    (OFF_A0 + A_BYTES)
#define OFF_B0    (OFF_A1 + A_BYTES)
#define OFF_B1    (OFF_B0 + B_BYTES)
#define GEMM_SMEM (OFF_B1 + B_BYTES)  // 99328 bytes

__global__ __launch_bounds__(256, 1) void gemm_bf16_kernel() {
    extern __shared__ char smem[];
    const uint32_t sb = smem_to_u32(smem);
    const int tid = threadIdx.x;
    const int wid = tid >> 5;
    const int lane = tid & 31;
    const int bm = blockIdx.y * 128;
    const int bn = blockIdx.x * 256;

    const int warp_m = (wid >> 2) * 64;   // 0 or 64
    const int warp_n = (wid & 3) * 64;    // 0..192

    if (tid < 64) {
        float4 v = *reinterpret_cast<const float4*>(g_c2 + bn + tid * 4);
        *reinterpret_cast<float4*>(smem + OFF_C2S + tid * 16) = v;
    }

    const uint32_t aoff[2] = {OFF_A0, OFF_A1};
    const uint32_t boff[2] = {OFF_B0, OFF_B1};

    auto load_chunk = [&](int c, int buf) {
        const int k0 = c * KC;
        #pragma unroll
        for (int i = 0; i < 4; i++) {                 // A: 1024 segs of 16B
            int s = tid + i * 256;
            int row = s >> 3, seg = s & 7;
            const char* g = reinterpret_cast<const char*>(
                g_Xb + (size_t)(bm + row) * DIM + k0) + seg * 16;
            cp_async16(sb + aoff[buf] + SWZ128(row * 128 + seg * 16), g);
        }
        #pragma unroll
        for (int i = 0; i < 8; i++) {                 // B: 2048 segs of 16B
            int s = tid + i * 256;
            int row = s >> 3, seg = s & 7;
            const char* g = reinterpret_cast<const char*>(
                g_CBb + (size_t)(bn + row) * DIM + k0) + seg * 16;
            cp_async16(sb + boff[buf] + SWZ128(row * 128 + seg * 16), g);
        }
        asm volatile("cp.async.commit_group;" ::: "memory");
    };

    float acc[4][8][4];
    #pragma unroll
    for (int mi = 0; mi < 4; mi++)
        #pragma unroll
        for (int nj = 0; nj < 8; nj++)
            #pragma unroll
            for (int e = 0; e < 4; e++) acc[mi][nj][e] = 0.f;

    // lane-derived ldmatrix address components
    const int a_row = (lane & 15);                 // + warp_m + mi*16
    const int a_kb  = (lane & 16) ? 16 : 0;        // + kk*32
    const int b_row = (lane & 7) + ((lane & 16) >> 1);  // + warp_n + nb2*16
    const int b_kb  = (lane & 8) << 1;             // + kk*32

    load_chunk(0, 0);

    for (int c = 0; c < NCHUNK; c++) {
        const int cur = c & 1;
        if (c + 1 < NCHUNK) {
            load_chunk(c + 1, (c + 1) & 1);
            asm volatile("cp.async.wait_group 1;" ::: "memory");
        } else {
            asm volatile("cp.async.wait_group 0;" ::: "memory");
        }
        __syncthreads();

        const uint32_t ab = sb + aoff[cur];
        const uint32_t bb = sb + boff[cur];
        #pragma unroll
        for (int kk = 0; kk < 4; kk++) {
            uint32_t afr[4][4];
            #pragma unroll
            for (int mi = 0; mi < 4; mi++) {
                uint32_t addr = ab + SWZ128((warp_m + mi * 16 + a_row) * 128
                                            + kk * 32 + a_kb);
                LDSM_X4(afr[mi][0], afr[mi][1], afr[mi][2], afr[mi][3], addr);
            }
            uint32_t bfr[8][2];
            #pragma unroll
            for (int nb2 = 0; nb2 < 4; nb2++) {
                uint32_t addr = bb + SWZ128((warp_n + nb2 * 16 + b_row) * 128
                                            + kk * 32 + b_kb);
                uint32_t r0, r1, r2, r3;
                LDSM_X4(r0, r1, r2, r3, addr);
                bfr[nb2 * 2 + 0][0] = r0; bfr[nb2 * 2 + 0][1] = r1;
                bfr[nb2 * 2 + 1][0] = r2; bfr[nb2 * 2 + 1][1] = r3;
            }
            #pragma unroll
            for (int mi = 0; mi < 4; mi++)
                #pragma unroll
                for (int nj = 0; nj < 8; nj++)
                    mma_bf16(acc[mi][nj], afr[mi], bfr[nj]);
        }
        __syncthreads();
    }

    // Epilogue: score = 2*acc - c2[n]
    const float* c2s = reinterpret_cast<const float*>(smem + OFF_C2S);
    const int r0 = lane >> 2;          // 0..7
    const int cl = (lane & 3) * 2;     // 0,2,4,6
    #pragma unroll
    for (int mi = 0; mi < 4; mi++) {
        const int mrow = bm + warp_m + mi * 16 + r0;
        float* out0 = g_scores + (size_t)mrow * CODES + bn;
        float* out1 = g_scores + (size_t)(mrow + 8) * CODES + bn;
        #pragma unroll
        for (int nj = 0; nj < 8; nj++) {
            const int col = warp_n + nj * 8 + cl;
            float2 v0, v1;
            v0.x = 2.f * acc[mi][nj][0] - c2s[col];
            v0.y = 2.f * acc[mi][nj][1] - c2s[col + 1];
            v1.x = 2.f * acc[mi][nj][2] - c2s[col];
            v1.y = 2.f * acc[mi][nj][3] - c2s[col + 1];
            *reinterpret_cast<float2*>(out0 + col) = v0;
            *reinterpret_cast<float2*>(out1 + col) = v1;
        }
    }
}

// ---------------------------------------------------------------------------
// Top-32 prefilter over approx scores (value desc, tie -> lower index)
// ---------------------------------------------------------------------------
__device__ __forceinline__ bool better(float va, int ia, float vb, int ib) {
    return (va > vb) || (va == vb && ia < ib);
}
__device__ __forceinline__ void merge_lists(
    const float* av, const int* ai, int la,
    const float* bv, const int* bi, int lb,
    float* ov, int* oi, int lo)
{
    int i = 0, j = 0;
    for (int o = 0; o < lo; o++) {
        bool ta;
        if (i >= la) ta = false;
        else if (j >= lb) ta = true;
        else ta = better(av[i], ai[i], bv[j], bi[j]);
        ov[o] = ta ? av[i] : bv[j];
        oi[o] = ta ? ai[i] : bi[j];
        if (ta) i++; else j++;
    }
}

__global__ __launch_bounds__(256) void topk32_kernel() {
    const int token = blockIdx.x;
    const int t = threadIdx.x;
    const float* srow = g_scores + (size_t)token * CODES;

    float v[KSEL]; int ix[KSEL];
    #pragma unroll
    for (int i = 0; i < KSEL; i++) { v[i] = -INFINITY; ix[i] = 0x7fffffff; }
    for (int n = t; n < CODES; n += 256) {
        float s = srow[n];
        if (better(s, n, v[KSEL - 1], ix[KSEL - 1])) {
            v[KSEL - 1] = s; ix[KSEL - 1] = n;
            #pragma unroll
            for (int i = KSEL - 1; i > 0; i--) {
                if (better(v[i], ix[i], v[i - 1], ix[i - 1])) {
                    float tv = v[i]; v[i] = v[i - 1]; v[i - 1] = tv;
                    int ti = ix[i]; ix[i] = ix[i - 1]; ix[i - 1] = ti;
                }
            }
        }
    }

    __shared__ float va[2048]; __shared__ int ia[2048];
    __shared__ float vb[2048]; __shared__ int ib[2048];
    #pragma unroll
    for (int i = 0; i < KSEL; i++) { va[t * 8 + i] = v[i]; ia[t * 8 + i] = ix[i]; }
    __syncthreads();

    if (t < 128)
        merge_lists(va + (2*t)*8, ia + (2*t)*8, 8, va + (2*t+1)*8, ia + (2*t+1)*8, 8,
                    vb + t*16, ib + t*16, 16);
    __syncthreads();
    if (t < 64)
        merge_lists(vb + (2*t)*16, ib + (2*t)*16, 16, vb + (2*t+1)*16, ib + (2*t+1)*16, 16,
                    va + t*32, ia + t*32, 32);
    __syncthreads();
    float* src_v = va; int* src_i = ia; float* dst_v = vb; int* dst_i = ib;
    for (int n = 32; n >= 1; n >>= 1) {
        if (t < n)
            merge_lists(src_v + (2*t)*32, src_i + (2*t)*32, 32,
                        src_v + (2*t+1)*32, src_i + (2*t+1)*32, 32,
                        dst_v + t*32, dst_i + t*32, 32);
        __syncthreads();
        float* tv = src_v; src_v = dst_v; dst_v = tv;
        int*   ti = src_i; src_i = dst_i; dst_i = ti;
    }
    if (t < NCAND) g_cand[token * NCAND + t] = src_i[t];
}

// ---------------------------------------------------------------------------
// Exact fp32 rescore of 32 candidates + top-8 select + gather/mean
// ---------------------------------------------------------------------------
__global__ __launch_bounds__(256) void rescore_kernel(
    const float* __restrict__ X, const float* __restrict__ CB,
    float* __restrict__ out, float* idsf, int* idsi, int write_main)
{
    const int token = blockIdx.x;
    const int tid = threadIdx.x;
    const int w = tid >> 5, lane = tid & 31;
    __shared__ float xs[DIM];
    __shared__ float cs[NCAND];
    __shared__ int   cid[NCAND];
    __shared__ int   sel[KSEL];

    reinterpret_cast<float4*>(xs)[tid] =
        reinterpret_cast<const float4*>(X + (size_t)token * DIM)[tid];
    if (tid < NCAND) cid[tid] = g_cand[token * NCAND + tid];
    __syncthreads();

    #pragma unroll
    for (int q = 0; q < 4; q++) {
        const int slot = w + q * 8;
        const int c = cid[slot];
        const float4* cp4 = reinterpret_cast<const float4*>(CB + (size_t)c * DIM);
        float acc = 0.f;
        #pragma unroll
        for (int u = 0; u < 8; u++) {
            float4 cv = cp4[lane + 32 * u];
            float4 xv = reinterpret_cast<const float4*>(xs)[lane + 32 * u];
            acc += xv.x * cv.x + xv.y * cv.y + xv.z * cv.z + xv.w * cv.w;
        }
        #pragma unroll
        for (int o = 16; o > 0; o >>= 1) acc += __shfl_down_sync(0xffffffffu, acc, o);
        if (lane == 0) cs[slot] = 2.f * acc - g_c2[c];
    }
    __syncthreads();

    if (tid == 0) {
        unsigned used = 0;
        #pragma unroll
        for (int k = 0; k < KSEL; k++) {
            float bv = -INFINITY; int bi = 0x7fffffff; int bs = -1;
            for (int i = 0; i < NCAND; i++) {
                if (used & (1u << i)) continue;
                if (better(cs[i], cid[i], bv, bi)) { bv = cs[i]; bi = cid[i]; bs = i; }
            }
            used |= (1u << bs);
            sel[k] = bi;
            g_ids[token * KSEL + k] = bi;
            if (idsf) idsf[token * KSEL + k] = (float)bi;
            if (idsi) idsi[token * KSEL + k] = bi;
        }
    }
    __syncthreads();

    if (write_main) {
        float4 acc = make_float4(0.f, 0.f, 0.f, 0.f);
        #pragma unroll
        for (int k = 0; k < KSEL; k++) {
            float4 cv = reinterpret_cast<const float4*>(CB + (size_t)sel[k] * DIM)[tid];
            acc.x += cv.x; acc.y += cv.y; acc.z += cv.z; acc.w += cv.w;
        }
        float4 r = make_float4(acc.x * 0.125f, acc.y * 0.125f,
                               acc.z * 0.125f, acc.w * 0.125f);
        reinterpret_cast<float4*>(out + (size_t)token * DIM)[tid] = r;
    }
}

// ---------------------------------------------------------------------------
// Launch
// ---------------------------------------------------------------------------
extern "C" void kernel_launch(void* const* d_in, const int* in_sizes, int n_in,
                              void* d_out, int out_size) {
    const float* inputs   = (const float*)d_in[0];
    const float* codebook = (const float*)d_in[1];
    float* out = (float*)d_out;

    convX_kernel<<<TOKENS * DIM / 1024, 256>>>(inputs);
    convCB_kernel<<<CODES * DIM / 1024, 256>>>(codebook);
    c2_kernel<<<CODES, 256>>>(codebook);

    // Unconditional (no static guard — harness rule). Idempotent, host-side,
    // not a stream op, so graph capture is unaffected.
    cudaFuncSetAttribute(gemm_bf16_kernel,
                         cudaFuncAttributeMaxDynamicSharedMemorySize, GEMM_SMEM);

    gemm_bf16_kernel<<<dim3(CODES / 256, TOKENS / 128), 256, GEMM_SMEM>>>();

    topk32_kernel<<<TOKENS, 256>>>();

    const int OUT_MAIN = TOKENS * DIM;
    const int OUT_IDS  = TOKENS * KSEL;
    float* idsf = nullptr; int* idsi = nullptr;
    int write_main = (out_size >= OUT_MAIN) ? 1 : 0;
    if (out_size == OUT_MAIN + OUT_IDS)      idsf = out + (size_t)OUT_MAIN;
    else if (out_size == OUT_IDS)            idsi = (int*)d_out;

    rescore_kernel<<<TOKENS, 256>>>(inputs, codebook, out, idsf, idsi, write_main);
}